// round 7
// baseline (speedup 1.0000x reference)
#include <cuda_runtime.h>
#include <cuda_bf16.h>
#include <math.h>

// ============================================================================
// GAT: 2-layer graph attention, N=8192, F_in=29, F_hid=8, H=4, F_out=2
//
// exp-free O(N^2) inner loop:
//   w_ij = exp(LReLU(f1_i+f2_j) - C_i) = max(E1p_i*E2p_j, E1n_i*E2n_j)
// f32x2-packed math; FMNMX/FSEL ride the ALU pipe.
// attn1: head-pair split across warp halves; regs capped for 3 CTAs/SM.
// ============================================================================

#define N_NODES   8192
#define F_IN      29
#define F_HID     8
#define N_HEADS   4
#define GAT_ALPHA 0.2f

#define NCH1      16                     // attn1 j-chunks
#define JCH1      (N_NODES / NCH1)       // 512
#define NCH2      16                     // attn2 j-chunks
#define JCH2      (N_NODES / NCH2)       // 512
#define TJ        128                    // attn1 SMEM tile of j's

typedef unsigned long long ull;

// ---------------------------------------------------------------------------
// f32x2 helpers
// ---------------------------------------------------------------------------
__device__ __forceinline__ ull f2mul(ull a, ull b) {
    ull r; asm("mul.rn.f32x2 %0, %1, %2;" : "=l"(r) : "l"(a), "l"(b)); return r;
}
__device__ __forceinline__ ull f2add(ull a, ull b) {
    ull r; asm("add.rn.f32x2 %0, %1, %2;" : "=l"(r) : "l"(a), "l"(b)); return r;
}
__device__ __forceinline__ ull f2fma(ull a, ull b, ull c) {
    ull r; asm("fma.rn.f32x2 %0, %1, %2, %3;" : "=l"(r) : "l"(a), "l"(b), "l"(c)); return r;
}
__device__ __forceinline__ float2 f2lohi(ull v) {
    float2 r; asm("mov.b64 {%0, %1}, %2;" : "=f"(r.x), "=f"(r.y) : "l"(v)); return r;
}
__device__ __forceinline__ ull f2pack(float x, float y) {
    ull r; asm("mov.b64 %0, {%1, %2};" : "=l"(r) : "f"(x), "f"(y)); return r;
}

// exact, order-independent float atomic max
__device__ __forceinline__ void atomicMaxF(float* addr, float v) {
    if (v >= 0.f) atomicMax((int*)addr, __float_as_int(v));
    else          atomicMin((unsigned int*)addr, __float_as_uint(v));
}

// ---------------------------------------------------------------------------
// Device scratch (static)
// ---------------------------------------------------------------------------
__device__ __align__(16) uint4 g_adjT4[(N_NODES / 128) * N_NODES];   // 8 MB [g128][i]
__device__ __align__(16) float g_tile1[N_NODES * 40];
__device__ __align__(16) float g_row1[N_NODES * 8];
__device__ float g_f1_1[N_NODES * N_HEADS];
__device__ float g_f2_1[N_NODES * N_HEADS];
__device__ float g_m2[8];
__device__ float g_part1[NCH1 * N_NODES * 36];
__device__ __align__(16) float g_tile2F[4 * N_NODES];
__device__ float g_row2[N_NODES * 2];
__device__ float g_f1_2[N_NODES];
__device__ float g_f2_2[N_NODES];
__device__ float g_part2[NCH2 * N_NODES * 4];

// ---------------------------------------------------------------------------
// K0: pack adj into uint4 bitmasks (permuted bit order, transposed) + init m2
// ---------------------------------------------------------------------------
__global__ void gat_pack_adj(const int* __restrict__ adj) {
    if (blockIdx.x == 0 && threadIdx.x < 8)
        g_m2[threadIdx.x] = __int_as_float(0xff800000);
    int gw   = (blockIdx.x * blockDim.x + threadIdx.x) >> 5;
    int lane = threadIdx.x & 31;
    int i = gw & (N_NODES - 1);
    int g = gw >> 13;
    const int4* p = (const int4*)(adj + (size_t)i * N_NODES + g * 128);
    int4 v = p[lane];
    unsigned m0 = __ballot_sync(0xFFFFFFFFu, v.x > 0);
    unsigned m1 = __ballot_sync(0xFFFFFFFFu, v.y > 0);
    unsigned m2 = __ballot_sync(0xFFFFFFFFu, v.z > 0);
    unsigned m3 = __ballot_sync(0xFFFFFFFFu, v.w > 0);
    if (lane == 0) g_adjT4[g * N_NODES + i] = make_uint4(m0, m1, m2, m3);
}

// ---------------------------------------------------------------------------
// K1: h = x@W per head, f1/f2, fused per-head max(f2)
// ---------------------------------------------------------------------------
__global__ void gat_prep1(const float* __restrict__ x,
                          const float* __restrict__ Wh,
                          const float* __restrict__ ah) {
    __shared__ float sW[N_HEADS * F_IN * F_HID];
    __shared__ float sa[N_HEADS * 2 * F_HID];
    for (int q = threadIdx.x; q < N_HEADS * F_IN * F_HID; q += blockDim.x) sW[q] = Wh[q];
    if (threadIdx.x < 64) sa[threadIdx.x] = ah[threadIdx.x];
    __syncthreads();

    int i = blockIdx.x * blockDim.x + threadIdx.x;
    int lane = threadIdx.x & 31;
    float xr[F_IN];
#pragma unroll
    for (int c = 0; c < F_IN; c++) xr[c] = x[i * F_IN + c];

#pragma unroll
    for (int h = 0; h < N_HEADS; h++) {
        float hv[F_HID];
#pragma unroll
        for (int k = 0; k < F_HID; k++) hv[k] = 0.f;
#pragma unroll
        for (int c = 0; c < F_IN; c++) {
            float xc = xr[c];
#pragma unroll
            for (int k = 0; k < F_HID; k++)
                hv[k] = fmaf(xc, sW[h * (F_IN * F_HID) + c * F_HID + k], hv[k]);
        }
        float f1 = 0.f, f2 = 0.f;
#pragma unroll
        for (int k = 0; k < F_HID; k++) {
            f1 = fmaf(hv[k], sa[h * 16 + k], f1);
            f2 = fmaf(hv[k], sa[h * 16 + 8 + k], f2);
        }
        int gp = h >> 1, o = h & 1;
#pragma unroll
        for (int k = 0; k < F_HID; k++)
            g_tile1[i * 40 + 8 + gp * 16 + k * 2 + o] = hv[k];
        g_f1_1[i * N_HEADS + h] = f1;
        g_f2_1[i * N_HEADS + h] = f2;
        float m = f2;
#pragma unroll
        for (int s = 16; s > 0; s >>= 1) m = fmaxf(m, __shfl_xor_sync(0xFFFFFFFFu, m, s));
        if (lane == 0) atomicMaxF(&g_m2[h], m);
    }
}

// ---------------------------------------------------------------------------
// K2: layer-1 E1/E2 factors
// ---------------------------------------------------------------------------
__global__ void gat_prep1b() {
    int i = blockIdx.x * blockDim.x + threadIdx.x;
#pragma unroll
    for (int h = 0; h < N_HEADS; h++) {
        int gp = h >> 1, o = h & 1;
        float m2 = g_m2[h];
        float t  = g_f1_1[i * N_HEADS + h] + m2;
        float C  = fmaxf(t, GAT_ALPHA * t);
        g_row1[i * 8 + gp * 4 + o]     = expf(t - C);
        g_row1[i * 8 + gp * 4 + 2 + o] = expf(GAT_ALPHA * t - C);
        float u = g_f2_1[i * N_HEADS + h] - m2;
        g_tile1[i * 40 + gp * 4 + o]     = expf(u);
        g_tile1[i * 40 + gp * 4 + 2 + o] = expf(GAT_ALPHA * u);
    }
}

// ---------------------------------------------------------------------------
// K3: layer-1 attention. 256 threads: warp-half = head-pair; 2 rows/thread.
// Register budget capped for 3 CTAs/SM.
// ---------------------------------------------------------------------------
__global__ void __launch_bounds__(256, 3) gat_attn1() {
    __shared__ __align__(16) float tile[TJ * 40];   // 20 KB

    int t  = threadIdx.x & 127;
    int hp = threadIdx.x >> 7;
    int i0 = blockIdx.x * 256 + t;
    int i1 = i0 + 128;
    int jbase = blockIdx.y * JCH1;

    ulonglong2 e0 = *(const ulonglong2*)(g_row1 + (size_t)i0 * 8 + hp * 4);
    ulonglong2 e1 = *(const ulonglong2*)(g_row1 + (size_t)i1 * 8 + hp * 4);

    ull den0 = 0, den1 = 0;
    ull acc0[F_HID], acc1[F_HID];
#pragma unroll
    for (int k = 0; k < F_HID; k++) { acc0[k] = 0; acc1[k] = 0; }

    for (int jt = 0; jt < JCH1; jt += TJ) {
        __syncthreads();
        const float4* src = (const float4*)(g_tile1 + (size_t)(jbase + jt) * 40);
        float4* dst = (float4*)tile;
#pragma unroll
        for (int q = 0; q < 5; q++) dst[threadIdx.x + q * 256] = src[threadIdx.x + q * 256];
        __syncthreads();

        int g = (jbase + jt) >> 7;
        uint4 B0 = g_adjT4[(size_t)g * N_NODES + i0];
        uint4 B1 = g_adjT4[(size_t)g * N_NODES + i1];
        unsigned mw0[4] = {B0.x, B0.y, B0.z, B0.w};
        unsigned mw1[4] = {B1.x, B1.y, B1.z, B1.w};

#pragma unroll
        for (int c = 0; c < 4; c++) {
            unsigned m0 = mw0[c], m1 = mw1[c];
#pragma unroll 4
            for (int l = 0; l < 32; l++) {
                const float* tr = tile + (4 * l + c) * 40;
                ulonglong2 E2 = *(const ulonglong2*)(tr + hp * 4);   // E2p, E2n

                ull wp0 = f2mul(e0.x, E2.x), wn0 = f2mul(e0.y, E2.y);
                ull wp1 = f2mul(e1.x, E2.x), wn1 = f2mul(e1.y, E2.y);
                float2 p0 = f2lohi(wp0), n0 = f2lohi(wn0);
                float2 p1 = f2lohi(wp1), n1 = f2lohi(wn1);
                bool a0 = (m0 >> l) & 1u;
                bool a1 = (m1 >> l) & 1u;
                float w00 = a0 ? fmaxf(p0.x, n0.x) : 0.f;
                float w01 = a0 ? fmaxf(p0.y, n0.y) : 0.f;
                float w10 = a1 ? fmaxf(p1.x, n1.x) : 0.f;
                float w11 = a1 ? fmaxf(p1.y, n1.y) : 0.f;
                ull w0 = f2pack(w00, w01);
                ull w1 = f2pack(w10, w11);
                den0 = f2add(den0, w0);
                den1 = f2add(den1, w1);

                const ulonglong2* hb = (const ulonglong2*)(tr + 8 + hp * 16);
#pragma unroll
                for (int q = 0; q < 4; q++) {
                    ulonglong2 u = hb[q];
                    acc0[2 * q]     = f2fma(w0, u.x, acc0[2 * q]);
                    acc0[2 * q + 1] = f2fma(w0, u.y, acc0[2 * q + 1]);
                    acc1[2 * q]     = f2fma(w1, u.x, acc1[2 * q]);
                    acc1[2 * q + 1] = f2fma(w1, u.y, acc1[2 * q + 1]);
                }
            }
        }
    }

    float* p0 = g_part1 + ((size_t)blockIdx.y * N_NODES + i0) * 36 + hp * 18;
    float* p1 = g_part1 + ((size_t)blockIdx.y * N_NODES + i1) * 36 + hp * 18;
#pragma unroll
    for (int k = 0; k < F_HID; k++) {
        float2 v;
        v = f2lohi(acc0[k]); p0[k] = v.x; p0[9 + k] = v.y;
        v = f2lohi(acc1[k]); p1[k] = v.x; p1[9 + k] = v.y;
    }
    {
        float2 v;
        v = f2lohi(den0); p0[8] = v.x; p0[17] = v.y;
        v = f2lohi(den1); p1[8] = v.x; p1[17] = v.y;
    }
}

// ---------------------------------------------------------------------------
// K4: combine layer-1 partials, ELU, layer-2 h/f1/f2, fused max(f2_2)
// ---------------------------------------------------------------------------
__global__ void gat_comb1(const float* __restrict__ Wout,
                          const float* __restrict__ aout) {
    int i = blockIdx.x * blockDim.x + threadIdx.x;
    int lane = threadIdx.x & 31;
    float den[N_HEADS];
    float acc[N_HEADS][F_HID];
#pragma unroll
    for (int h = 0; h < N_HEADS; h++) {
        den[h] = 0.f;
#pragma unroll
        for (int k = 0; k < F_HID; k++) acc[h][k] = 0.f;
    }
    for (int c = 0; c < NCH1; c++) {
        const float* p = g_part1 + ((size_t)c * N_NODES + i) * 36;
#pragma unroll
        for (int h = 0; h < N_HEADS; h++) {
#pragma unroll
            for (int k = 0; k < F_HID; k++) acc[h][k] += p[h * 9 + k];
            den[h] += p[h * 9 + 8];
        }
    }
    float hc[N_HEADS * F_HID];
#pragma unroll
    for (int h = 0; h < N_HEADS; h++) {
        float inv = 1.0f / den[h];
#pragma unroll
        for (int k = 0; k < F_HID; k++) {
            float o = acc[h][k] * inv;
            hc[h * 8 + k] = (o > 0.f) ? o : expm1f(o);
        }
    }
    float h2_0 = 0.f, h2_1 = 0.f;
#pragma unroll
    for (int q = 0; q < 32; q++) {
        h2_0 = fmaf(hc[q], __ldg(&Wout[q * 2 + 0]), h2_0);
        h2_1 = fmaf(hc[q], __ldg(&Wout[q * 2 + 1]), h2_1);
    }
    float a0 = __ldg(&aout[0]), a1 = __ldg(&aout[1]);
    float a2 = __ldg(&aout[2]), a3 = __ldg(&aout[3]);
    g_tile2F[2 * N_NODES + i] = h2_0;
    g_tile2F[3 * N_NODES + i] = h2_1;
    g_f1_2[i] = h2_0 * a0 + h2_1 * a1;
    float f2 = h2_0 * a2 + h2_1 * a3;
    g_f2_2[i] = f2;
    float m = f2;
#pragma unroll
    for (int s = 16; s > 0; s >>= 1) m = fmaxf(m, __shfl_xor_sync(0xFFFFFFFFu, m, s));
    if (lane == 0) atomicMaxF(&g_m2[4], m);
}

// ---------------------------------------------------------------------------
// K5: layer-2 E1/E2
// ---------------------------------------------------------------------------
__global__ void gat_prep2() {
    int i = blockIdx.x * blockDim.x + threadIdx.x;
    float m2 = g_m2[4];
    float t = g_f1_2[i] + m2;
    float C = fmaxf(t, GAT_ALPHA * t);
    g_row2[i * 2]     = expf(t - C);
    g_row2[i * 2 + 1] = expf(GAT_ALPHA * t - C);
    float u = g_f2_2[i] - m2;
    g_tile2F[0 * N_NODES + i] = expf(u);
    g_tile2F[1 * N_NODES + i] = expf(GAT_ALPHA * u);
}

// ---------------------------------------------------------------------------
// K6: layer-2 attention. 2 rows/thread, j-pairs packed, chunk 512 in SMEM.
// ---------------------------------------------------------------------------
__global__ void __launch_bounds__(128, 6) gat_attn2() {
    __shared__ __align__(16) float tE[4][JCH2];   // 8 KB
    int t = threadIdx.x;
    int i0 = blockIdx.x * 256 + t;
    int i1 = i0 + 128;
    int jbase = blockIdx.y * JCH2;

#pragma unroll
    for (int f = 0; f < 4; f++) {
        const float4* src = (const float4*)(g_tile2F + (size_t)f * N_NODES + jbase);
        float4* dst = (float4*)tE[f];
#pragma unroll
        for (int q = 0; q < JCH2 / 512; q++) dst[t + q * 128] = src[t + q * 128];
    }
    __syncthreads();

    ull e1p0 = f2pack(g_row2[i0 * 2], g_row2[i0 * 2]);
    ull e1n0 = f2pack(g_row2[i0 * 2 + 1], g_row2[i0 * 2 + 1]);
    ull e1p1 = f2pack(g_row2[i1 * 2], g_row2[i1 * 2]);
    ull e1n1 = f2pack(g_row2[i1 * 2 + 1], g_row2[i1 * 2 + 1]);

    ull den0 = 0, a00 = 0, a10 = 0;
    ull den1 = 0, a01 = 0, a11 = 0;

    for (int jt = 0; jt < JCH2; jt += 128) {
        int g = (jbase + jt) >> 7;
        uint4 B0 = g_adjT4[(size_t)g * N_NODES + i0];
        uint4 B1 = g_adjT4[(size_t)g * N_NODES + i1];
        unsigned mw0[4] = {B0.x, B0.y, B0.z, B0.w};
        unsigned mw1[4] = {B1.x, B1.y, B1.z, B1.w};

#pragma unroll
        for (int cc = 0; cc < 4; cc += 2) {
            unsigned m0a = mw0[cc], m0b = mw0[cc + 1];
            unsigned m1a = mw1[cc], m1b = mw1[cc + 1];
#pragma unroll 8
            for (int l = 0; l < 32; l++) {
                int jloc = jt + 4 * l + cc;
                ull E2p2 = *(const ull*)(&tE[0][jloc]);
                ull E2n2 = *(const ull*)(&tE[1][jloc]);
                ull H02  = *(const ull*)(&tE[2][jloc]);
                ull H12  = *(const ull*)(&tE[3][jloc]);
                bool a0a = (m0a >> l) & 1u, a0b = (m0b >> l) & 1u;
                bool a1a = (m1a >> l) & 1u, a1b = (m1b >> l) & 1u;

                ull wp0 = f2mul(e1p0, E2p2), wn0 = f2mul(e1n0, E2n2);
                ull wp1 = f2mul(e1p1, E2p2), wn1 = f2mul(e1n1, E2n2);
                float2 p0 = f2lohi(wp0), n0 = f2lohi(wn0);
                float2 p1 = f2lohi(wp1), n1 = f2lohi(wn1);
                float w00 = a0a ? fmaxf(p0.x, n0.x) : 0.f;
                float w01 = a0b ? fmaxf(p0.y, n0.y) : 0.f;
                float w10 = a1a ? fmaxf(p1.x, n1.x) : 0.f;
                float w11 = a1b ? fmaxf(p1.y, n1.y) : 0.f;
                ull w0 = f2pack(w00, w01), w1 = f2pack(w10, w11);
                den0 = f2add(den0, w0);
                a00 = f2fma(w0, H02, a00);
                a10 = f2fma(w0, H12, a10);
                den1 = f2add(den1, w1);
                a01 = f2fma(w1, H02, a01);
                a11 = f2fma(w1, H12, a11);
            }
        }
    }

    {
        float2 d = f2lohi(den0), x0 = f2lohi(a00), x1 = f2lohi(a10);
        float* p = g_part2 + ((size_t)blockIdx.y * N_NODES + i0) * 4;
        p[0] = d.x + d.y; p[1] = x0.x + x0.y; p[2] = x1.x + x1.y;
    }
    {
        float2 d = f2lohi(den1), x0 = f2lohi(a01), x1 = f2lohi(a11);
        float* p = g_part2 + ((size_t)blockIdx.y * N_NODES + i1) * 4;
        p[0] = d.x + d.y; p[1] = x0.x + x0.y; p[2] = x1.x + x1.y;
    }
}

// ---------------------------------------------------------------------------
// K7: combine, ELU, log_softmax
// ---------------------------------------------------------------------------
__global__ void gat_final(float* __restrict__ out) {
    int i = blockIdx.x * blockDim.x + threadIdx.x;
    float den = 0.f, a0 = 0.f, a1 = 0.f;
    for (int c = 0; c < NCH2; c++) {
        const float* p = g_part2 + ((size_t)c * N_NODES + i) * 4;
        den += p[0]; a0 += p[1]; a1 += p[2];
    }
    float inv = 1.0f / den;
    float o0 = a0 * inv; o0 = (o0 > 0.f) ? o0 : expm1f(o0);
    float o1 = a1 * inv; o1 = (o1 > 0.f) ? o1 : expm1f(o1);
    float m = fmaxf(o0, o1);
    float l = logf(expf(o0 - m) + expf(o1 - m)) + m;
    out[i * 2]     = o0 - l;
    out[i * 2 + 1] = o1 - l;
}

// ---------------------------------------------------------------------------
// launch (attn1 is launch #4 for the ncu window)
// ---------------------------------------------------------------------------
extern "C" void kernel_launch(void* const* d_in, const int* in_sizes, int n_in,
                              void* d_out, int out_size) {
    const float* x  = nullptr;
    const int*   adj = nullptr;
    const float* Wh = nullptr;
    const float* ah = nullptr;
    const float* Wo = nullptr;
    const float* ao = nullptr;
    int found64 = 0;
    for (int k = 0; k < n_in; k++) {
        long s = in_sizes[k];
        if (s == (long)N_NODES * F_IN)          x   = (const float*)d_in[k];
        else if (s == (long)N_NODES * N_NODES)  adj = (const int*)d_in[k];
        else if (s == N_HEADS * F_IN * F_HID)   Wh  = (const float*)d_in[k];
        else if (s == 64) { if (found64++ == 0) ah = (const float*)d_in[k]; else Wo = (const float*)d_in[k]; }
        else if (s == 4)                        ao  = (const float*)d_in[k];
    }

    gat_pack_adj<<<65536, 256>>>(adj);
    gat_prep1<<<N_NODES / 128, 128>>>(x, Wh, ah);
    gat_prep1b<<<N_NODES / 128, 128>>>();
    gat_attn1<<<dim3(N_NODES / 256, NCH1), 256>>>();
    gat_comb1<<<N_NODES / 128, 128>>>(Wo, ao);
    gat_prep2<<<N_NODES / 128, 128>>>();
    gat_attn2<<<dim3(N_NODES / 256, NCH2), 128>>>();
    gat_final<<<N_NODES / 128, 128>>>((float*)d_out);
    (void)out_size;
}

// round 9
// speedup vs baseline: 1.1195x; 1.1195x over previous
#include <cuda_runtime.h>
#include <cuda_bf16.h>
#include <math.h>

// ============================================================================
// GAT: 2-layer graph attention, N=8192, F_in=29, F_hid=8, H=4, F_out=2
//
// exp-free O(N^2) inner loop:
//   w_ij = exp(LReLU(f1_i+f2_j) - C_i) = max(E1p_i*E2p_j, E1n_i*E2n_j)
// f32x2-packed math; FMNMX/FSEL ride the ALU pipe.
// attn1: 128-thr CTAs (64 rows x 2 head-pair halves), 1024-CTA grid for
// ~99% wave utilization at 4 CTAs/SM.
// ============================================================================

#define N_NODES   8192
#define F_IN      29
#define F_HID     8
#define N_HEADS   4
#define GAT_ALPHA 0.2f

#define NCH1      16                     // attn1 j-chunks
#define JCH1      (N_NODES / NCH1)       // 512
#define NCH2      16                     // attn2 j-chunks
#define JCH2      (N_NODES / NCH2)       // 512
#define TJ        128                    // attn1 SMEM tile of j's

typedef unsigned long long ull;

// ---------------------------------------------------------------------------
// f32x2 helpers
// ---------------------------------------------------------------------------
__device__ __forceinline__ ull f2mul(ull a, ull b) {
    ull r; asm("mul.rn.f32x2 %0, %1, %2;" : "=l"(r) : "l"(a), "l"(b)); return r;
}
__device__ __forceinline__ ull f2add(ull a, ull b) {
    ull r; asm("add.rn.f32x2 %0, %1, %2;" : "=l"(r) : "l"(a), "l"(b)); return r;
}
__device__ __forceinline__ ull f2fma(ull a, ull b, ull c) {
    ull r; asm("fma.rn.f32x2 %0, %1, %2, %3;" : "=l"(r) : "l"(a), "l"(b), "l"(c)); return r;
}
__device__ __forceinline__ float2 f2lohi(ull v) {
    float2 r; asm("mov.b64 {%0, %1}, %2;" : "=f"(r.x), "=f"(r.y) : "l"(v)); return r;
}
__device__ __forceinline__ ull f2pack(float x, float y) {
    ull r; asm("mov.b64 %0, {%1, %2};" : "=l"(r) : "f"(x), "f"(y)); return r;
}

// exact, order-independent float atomic max
__device__ __forceinline__ void atomicMaxF(float* addr, float v) {
    if (v >= 0.f) atomicMax((int*)addr, __float_as_int(v));
    else          atomicMin((unsigned int*)addr, __float_as_uint(v));
}

// ---------------------------------------------------------------------------
// Device scratch (static)
// ---------------------------------------------------------------------------
__device__ __align__(16) uint4 g_adjT4[(N_NODES / 128) * N_NODES];   // 8 MB [g128][i]
__device__ __align__(16) float g_tile1[N_NODES * 40];
__device__ __align__(16) float g_row1[N_NODES * 8];
__device__ float g_f1_1[N_NODES * N_HEADS];
__device__ float g_f2_1[N_NODES * N_HEADS];
__device__ float g_m2[8];
__device__ float g_part1[NCH1 * N_NODES * 36];
__device__ __align__(16) float g_tile2F[4 * N_NODES];
__device__ float g_row2[N_NODES * 2];
__device__ float g_f1_2[N_NODES];
__device__ float g_f2_2[N_NODES];
__device__ float g_part2[NCH2 * N_NODES * 4];

// ---------------------------------------------------------------------------
// K0: pack adj into uint4 bitmasks (permuted bit order, transposed) + init m2
// ---------------------------------------------------------------------------
__global__ void gat_pack_adj(const int* __restrict__ adj) {
    if (blockIdx.x == 0 && threadIdx.x < 8)
        g_m2[threadIdx.x] = __int_as_float(0xff800000);
    int gw   = (blockIdx.x * blockDim.x + threadIdx.x) >> 5;
    int lane = threadIdx.x & 31;
    int i = gw & (N_NODES - 1);
    int g = gw >> 13;
    const int4* p = (const int4*)(adj + (size_t)i * N_NODES + g * 128);
    int4 v = p[lane];
    unsigned m0 = __ballot_sync(0xFFFFFFFFu, v.x > 0);
    unsigned m1 = __ballot_sync(0xFFFFFFFFu, v.y > 0);
    unsigned m2 = __ballot_sync(0xFFFFFFFFu, v.z > 0);
    unsigned m3 = __ballot_sync(0xFFFFFFFFu, v.w > 0);
    if (lane == 0) g_adjT4[g * N_NODES + i] = make_uint4(m0, m1, m2, m3);
}

// ---------------------------------------------------------------------------
// K1: h = x@W per head, f1/f2, fused per-head max(f2)
// ---------------------------------------------------------------------------
__global__ void gat_prep1(const float* __restrict__ x,
                          const float* __restrict__ Wh,
                          const float* __restrict__ ah) {
    __shared__ float sW[N_HEADS * F_IN * F_HID];
    __shared__ float sa[N_HEADS * 2 * F_HID];
    for (int q = threadIdx.x; q < N_HEADS * F_IN * F_HID; q += blockDim.x) sW[q] = Wh[q];
    if (threadIdx.x < 64) sa[threadIdx.x] = ah[threadIdx.x];
    __syncthreads();

    int i = blockIdx.x * blockDim.x + threadIdx.x;
    int lane = threadIdx.x & 31;
    float xr[F_IN];
#pragma unroll
    for (int c = 0; c < F_IN; c++) xr[c] = x[i * F_IN + c];

#pragma unroll
    for (int h = 0; h < N_HEADS; h++) {
        float hv[F_HID];
#pragma unroll
        for (int k = 0; k < F_HID; k++) hv[k] = 0.f;
#pragma unroll
        for (int c = 0; c < F_IN; c++) {
            float xc = xr[c];
#pragma unroll
            for (int k = 0; k < F_HID; k++)
                hv[k] = fmaf(xc, sW[h * (F_IN * F_HID) + c * F_HID + k], hv[k]);
        }
        float f1 = 0.f, f2 = 0.f;
#pragma unroll
        for (int k = 0; k < F_HID; k++) {
            f1 = fmaf(hv[k], sa[h * 16 + k], f1);
            f2 = fmaf(hv[k], sa[h * 16 + 8 + k], f2);
        }
        int gp = h >> 1, o = h & 1;
#pragma unroll
        for (int k = 0; k < F_HID; k++)
            g_tile1[i * 40 + 8 + gp * 16 + k * 2 + o] = hv[k];
        g_f1_1[i * N_HEADS + h] = f1;
        g_f2_1[i * N_HEADS + h] = f2;
        float m = f2;
#pragma unroll
        for (int s = 16; s > 0; s >>= 1) m = fmaxf(m, __shfl_xor_sync(0xFFFFFFFFu, m, s));
        if (lane == 0) atomicMaxF(&g_m2[h], m);
    }
}

// ---------------------------------------------------------------------------
// K2: layer-1 E1/E2 factors
// ---------------------------------------------------------------------------
__global__ void gat_prep1b() {
    int i = blockIdx.x * blockDim.x + threadIdx.x;
#pragma unroll
    for (int h = 0; h < N_HEADS; h++) {
        int gp = h >> 1, o = h & 1;
        float m2 = g_m2[h];
        float t  = g_f1_1[i * N_HEADS + h] + m2;
        float C  = fmaxf(t, GAT_ALPHA * t);
        g_row1[i * 8 + gp * 4 + o]     = expf(t - C);
        g_row1[i * 8 + gp * 4 + 2 + o] = expf(GAT_ALPHA * t - C);
        float u = g_f2_1[i * N_HEADS + h] - m2;
        g_tile1[i * 40 + gp * 4 + o]     = expf(u);
        g_tile1[i * 40 + gp * 4 + 2 + o] = expf(GAT_ALPHA * u);
    }
}

// ---------------------------------------------------------------------------
// head-pair update: 2 heads, 1 row, 1 j. fma pipe: 2 MUL2 + 1 ADD2 + 8 FFMA2.
// ---------------------------------------------------------------------------
__device__ __forceinline__ void hp_update(ull e1p, ull e1n, ull E2p, ull E2n,
                                          bool a, ull& den, ull* acc, const ull* hrow) {
    ull wp = f2mul(e1p, E2p);
    ull wn = f2mul(e1n, E2n);
    float2 p = f2lohi(wp), n = f2lohi(wn);
    float w0 = fmaxf(p.x, n.x); w0 = a ? w0 : 0.f;
    float w1 = fmaxf(p.y, n.y); w1 = a ? w1 : 0.f;
    ull w = f2pack(w0, w1);
    den = f2add(den, w);
#pragma unroll
    for (int k = 0; k < F_HID; k++) acc[k] = f2fma(w, hrow[k], acc[k]);
}

// ---------------------------------------------------------------------------
// K3: layer-1 attention. 128 threads: warps 0-1 = head-pair 0, warps 2-3 =
// head-pair 1. Each thread: 2 rows (i0, i0+64); CTA covers 128 rows.
// Grid (64, NCH1) = 1024 CTAs -> ~99% wave utilization at 4 CTAs/SM.
// ---------------------------------------------------------------------------
__global__ void __launch_bounds__(128, 4) gat_attn1() {
    __shared__ __align__(16) float tile[TJ * 40];   // 20 KB

    int t  = threadIdx.x & 63;
    int hp = threadIdx.x >> 6;        // 0 or 1
    int i0 = blockIdx.x * 128 + t;
    int i1 = i0 + 64;
    int jbase = blockIdx.y * JCH1;

    ulonglong2 e0 = *(const ulonglong2*)(g_row1 + (size_t)i0 * 8 + hp * 4);  // e1p, e1n
    ulonglong2 e1 = *(const ulonglong2*)(g_row1 + (size_t)i1 * 8 + hp * 4);

    ull den0 = 0, den1 = 0;
    ull acc0[F_HID], acc1[F_HID];
#pragma unroll
    for (int k = 0; k < F_HID; k++) { acc0[k] = 0; acc1[k] = 0; }

    for (int jt = 0; jt < JCH1; jt += TJ) {
        __syncthreads();
        // tile: 128 j * 40 floats = 1280 float4, 128 threads -> 10 each
        const float4* src = (const float4*)(g_tile1 + (size_t)(jbase + jt) * 40);
        float4* dst = (float4*)tile;
#pragma unroll
        for (int q = 0; q < 10; q++) dst[threadIdx.x + q * 128] = src[threadIdx.x + q * 128];
        __syncthreads();

        int g = (jbase + jt) >> 7;
        uint4 B0 = g_adjT4[(size_t)g * N_NODES + i0];
        uint4 B1 = g_adjT4[(size_t)g * N_NODES + i1];
        unsigned mw0[4] = {B0.x, B0.y, B0.z, B0.w};
        unsigned mw1[4] = {B1.x, B1.y, B1.z, B1.w};

#pragma unroll
        for (int c = 0; c < 4; c++) {
            unsigned m0 = mw0[c], m1 = mw1[c];
#pragma unroll 8
            for (int l = 0; l < 32; l++) {
                const float* tr = tile + (4 * l + c) * 40;
                bool a0 = (m0 >> l) & 1u;
                bool a1 = (m1 >> l) & 1u;

                ulonglong2 E2 = *(const ulonglong2*)(tr + hp * 4);   // E2p, E2n
                ull hrow[F_HID];
                {
                    const ulonglong2* hb = (const ulonglong2*)(tr + 8 + hp * 16);
                    ulonglong2 u0 = hb[0], u1 = hb[1], u2 = hb[2], u3 = hb[3];
                    hrow[0] = u0.x; hrow[1] = u0.y; hrow[2] = u1.x; hrow[3] = u1.y;
                    hrow[4] = u2.x; hrow[5] = u2.y; hrow[6] = u3.x; hrow[7] = u3.y;
                }
                hp_update(e0.x, e0.y, E2.x, E2.y, a0, den0, acc0, hrow);
                hp_update(e1.x, e1.y, E2.x, E2.y, a1, den1, acc1, hrow);
            }
        }
    }

    // partials: heads 2hp (lo) and 2hp+1 (hi)
    float* p0 = g_part1 + ((size_t)blockIdx.y * N_NODES + i0) * 36 + hp * 18;
    float* p1 = g_part1 + ((size_t)blockIdx.y * N_NODES + i1) * 36 + hp * 18;
#pragma unroll
    for (int k = 0; k < F_HID; k++) {
        float2 v;
        v = f2lohi(acc0[k]); p0[k] = v.x; p0[9 + k] = v.y;
        v = f2lohi(acc1[k]); p1[k] = v.x; p1[9 + k] = v.y;
    }
    {
        float2 v;
        v = f2lohi(den0); p0[8] = v.x; p0[17] = v.y;
        v = f2lohi(den1); p1[8] = v.x; p1[17] = v.y;
    }
}

// ---------------------------------------------------------------------------
// K4: combine layer-1 partials, ELU, layer-2 h/f1/f2, fused max(f2_2)
// ---------------------------------------------------------------------------
__global__ void gat_comb1(const float* __restrict__ Wout,
                          const float* __restrict__ aout) {
    int i = blockIdx.x * blockDim.x + threadIdx.x;
    int lane = threadIdx.x & 31;
    float den[N_HEADS];
    float acc[N_HEADS][F_HID];
#pragma unroll
    for (int h = 0; h < N_HEADS; h++) {
        den[h] = 0.f;
#pragma unroll
        for (int k = 0; k < F_HID; k++) acc[h][k] = 0.f;
    }
    for (int c = 0; c < NCH1; c++) {
        const float* p = g_part1 + ((size_t)c * N_NODES + i) * 36;
#pragma unroll
        for (int h = 0; h < N_HEADS; h++) {
#pragma unroll
            for (int k = 0; k < F_HID; k++) acc[h][k] += p[h * 9 + k];
            den[h] += p[h * 9 + 8];
        }
    }
    float hc[N_HEADS * F_HID];
#pragma unroll
    for (int h = 0; h < N_HEADS; h++) {
        float inv = 1.0f / den[h];
#pragma unroll
        for (int k = 0; k < F_HID; k++) {
            float o = acc[h][k] * inv;
            hc[h * 8 + k] = (o > 0.f) ? o : expm1f(o);
        }
    }
    float h2_0 = 0.f, h2_1 = 0.f;
#pragma unroll
    for (int q = 0; q < 32; q++) {
        h2_0 = fmaf(hc[q], __ldg(&Wout[q * 2 + 0]), h2_0);
        h2_1 = fmaf(hc[q], __ldg(&Wout[q * 2 + 1]), h2_1);
    }
    float a0 = __ldg(&aout[0]), a1 = __ldg(&aout[1]);
    float a2 = __ldg(&aout[2]), a3 = __ldg(&aout[3]);
    g_tile2F[2 * N_NODES + i] = h2_0;
    g_tile2F[3 * N_NODES + i] = h2_1;
    g_f1_2[i] = h2_0 * a0 + h2_1 * a1;
    float f2 = h2_0 * a2 + h2_1 * a3;
    g_f2_2[i] = f2;
    float m = f2;
#pragma unroll
    for (int s = 16; s > 0; s >>= 1) m = fmaxf(m, __shfl_xor_sync(0xFFFFFFFFu, m, s));
    if (lane == 0) atomicMaxF(&g_m2[4], m);
}

// ---------------------------------------------------------------------------
// K5: layer-2 E1/E2
// ---------------------------------------------------------------------------
__global__ void gat_prep2() {
    int i = blockIdx.x * blockDim.x + threadIdx.x;
    float m2 = g_m2[4];
    float t = g_f1_2[i] + m2;
    float C = fmaxf(t, GAT_ALPHA * t);
    g_row2[i * 2]     = expf(t - C);
    g_row2[i * 2 + 1] = expf(GAT_ALPHA * t - C);
    float u = g_f2_2[i] - m2;
    g_tile2F[0 * N_NODES + i] = expf(u);
    g_tile2F[1 * N_NODES + i] = expf(GAT_ALPHA * u);
}

// ---------------------------------------------------------------------------
// K6: layer-2 attention. 2 rows/thread, j-pairs packed, chunk 512 in SMEM.
// Grid (32, NCH2) = 512 CTAs of 128 threads.
// ---------------------------------------------------------------------------
__global__ void __launch_bounds__(128, 6) gat_attn2() {
    __shared__ __align__(16) float tE[4][JCH2];   // 8 KB
    int t = threadIdx.x;
    int i0 = blockIdx.x * 256 + t;
    int i1 = i0 + 128;
    int jbase = blockIdx.y * JCH2;

#pragma unroll
    for (int f = 0; f < 4; f++) {
        const float4* src = (const float4*)(g_tile2F + (size_t)f * N_NODES + jbase);
        float4* dst = (float4*)tE[f];
        dst[t] = src[t];   // 512 floats = 128 float4 per field
    }
    __syncthreads();

    ull e1p0 = f2pack(g_row2[i0 * 2], g_row2[i0 * 2]);
    ull e1n0 = f2pack(g_row2[i0 * 2 + 1], g_row2[i0 * 2 + 1]);
    ull e1p1 = f2pack(g_row2[i1 * 2], g_row2[i1 * 2]);
    ull e1n1 = f2pack(g_row2[i1 * 2 + 1], g_row2[i1 * 2 + 1]);

    ull den0 = 0, a00 = 0, a10 = 0;
    ull den1 = 0, a01 = 0, a11 = 0;

    for (int jt = 0; jt < JCH2; jt += 128) {
        int g = (jbase + jt) >> 7;
        uint4 B0 = g_adjT4[(size_t)g * N_NODES + i0];
        uint4 B1 = g_adjT4[(size_t)g * N_NODES + i1];
        unsigned mw0[4] = {B0.x, B0.y, B0.z, B0.w};
        unsigned mw1[4] = {B1.x, B1.y, B1.z, B1.w};

#pragma unroll
        for (int cc = 0; cc < 4; cc += 2) {
            unsigned m0a = mw0[cc], m0b = mw0[cc + 1];
            unsigned m1a = mw1[cc], m1b = mw1[cc + 1];
#pragma unroll 8
            for (int l = 0; l < 32; l++) {
                int jloc = jt + 4 * l + cc;
                ull E2p2 = *(const ull*)(&tE[0][jloc]);
                ull E2n2 = *(const ull*)(&tE[1][jloc]);
                ull H02  = *(const ull*)(&tE[2][jloc]);
                ull H12  = *(const ull*)(&tE[3][jloc]);
                bool a0a = (m0a >> l) & 1u, a0b = (m0b >> l) & 1u;
                bool a1a = (m1a >> l) & 1u, a1b = (m1b >> l) & 1u;

                ull wp0 = f2mul(e1p0, E2p2), wn0 = f2mul(e1n0, E2n2);
                ull wp1 = f2mul(e1p1, E2p2), wn1 = f2mul(e1n1, E2n2);
                float2 p0 = f2lohi(wp0), n0 = f2lohi(wn0);
                float2 p1 = f2lohi(wp1), n1 = f2lohi(wn1);
                float w00 = a0a ? fmaxf(p0.x, n0.x) : 0.f;
                float w01 = a0b ? fmaxf(p0.y, n0.y) : 0.f;
                float w10 = a1a ? fmaxf(p1.x, n1.x) : 0.f;
                float w11 = a1b ? fmaxf(p1.y, n1.y) : 0.f;
                ull w0 = f2pack(w00, w01), w1 = f2pack(w10, w11);
                den0 = f2add(den0, w0);
                a00 = f2fma(w0, H02, a00);
                a10 = f2fma(w0, H12, a10);
                den1 = f2add(den1, w1);
                a01 = f2fma(w1, H02, a01);
                a11 = f2fma(w1, H12, a11);
            }
        }
    }

    {
        float2 d = f2lohi(den0), x0 = f2lohi(a00), x1 = f2lohi(a10);
        float* p = g_part2 + ((size_t)blockIdx.y * N_NODES + i0) * 4;
        p[0] = d.x + d.y; p[1] = x0.x + x0.y; p[2] = x1.x + x1.y;
    }
    {
        float2 d = f2lohi(den1), x0 = f2lohi(a01), x1 = f2lohi(a11);
        float* p = g_part2 + ((size_t)blockIdx.y * N_NODES + i1) * 4;
        p[0] = d.x + d.y; p[1] = x0.x + x0.y; p[2] = x1.x + x1.y;
    }
}

// ---------------------------------------------------------------------------
// K7: combine, ELU, log_softmax
// ---------------------------------------------------------------------------
__global__ void gat_final(float* __restrict__ out) {
    int i = blockIdx.x * blockDim.x + threadIdx.x;
    float den = 0.f, a0 = 0.f, a1 = 0.f;
    for (int c = 0; c < NCH2; c++) {
        const float* p = g_part2 + ((size_t)c * N_NODES + i) * 4;
        den += p[0]; a0 += p[1]; a1 += p[2];
    }
    float inv = 1.0f / den;
    float o0 = a0 * inv; o0 = (o0 > 0.f) ? o0 : expm1f(o0);
    float o1 = a1 * inv; o1 = (o1 > 0.f) ? o1 : expm1f(o1);
    float m = fmaxf(o0, o1);
    float l = logf(expf(o0 - m) + expf(o1 - m)) + m;
    out[i * 2]     = o0 - l;
    out[i * 2 + 1] = o1 - l;
}

// ---------------------------------------------------------------------------
// launch (attn1 is launch #4 for the ncu window)
// ---------------------------------------------------------------------------
extern "C" void kernel_launch(void* const* d_in, const int* in_sizes, int n_in,
                              void* d_out, int out_size) {
    const float* x  = nullptr;
    const int*   adj = nullptr;
    const float* Wh = nullptr;
    const float* ah = nullptr;
    const float* Wo = nullptr;
    const float* ao = nullptr;
    int found64 = 0;
    for (int k = 0; k < n_in; k++) {
        long s = in_sizes[k];
        if (s == (long)N_NODES * F_IN)          x   = (const float*)d_in[k];
        else if (s == (long)N_NODES * N_NODES)  adj = (const int*)d_in[k];
        else if (s == N_HEADS * F_IN * F_HID)   Wh  = (const float*)d_in[k];
        else if (s == 64) { if (found64++ == 0) ah = (const float*)d_in[k]; else Wo = (const float*)d_in[k]; }
        else if (s == 4)                        ao  = (const float*)d_in[k];
    }

    gat_pack_adj<<<65536, 256>>>(adj);
    gat_prep1<<<N_NODES / 128, 128>>>(x, Wh, ah);
    gat_prep1b<<<N_NODES / 128, 128>>>();
    gat_attn1<<<dim3(N_NODES / 128, NCH1), 128>>>();
    gat_comb1<<<N_NODES / 128, 128>>>(Wo, ao);
    gat_prep2<<<N_NODES / 128, 128>>>();
    gat_attn2<<<dim3(N_NODES / 256, NCH2), 128>>>();
    gat_final<<<N_NODES / 128, 128>>>((float*)d_out);
    (void)out_size;
}